// round 4
// baseline (speedup 1.0000x reference)
#include <cuda_runtime.h>

#define N_NODES 100000
#define N_EDGES 1600000
#define IN_DIM 128
#define HID 32
#define BN_EPS 1e-5f
#define CAP 96   // max in-degree capacity (Poisson(16); P(deg>=96) ~ 1e-46); 16B-aligned, %4==0

// ---- scratch (static device globals; no allocation allowed) ----
__device__ __align__(128) int   g_cnt[N_NODES];          // in-degree (excl. self loop)
__device__ __align__(128) int   g_slots[N_NODES * CAP];  // buckets: src ids per dst
__device__ __align__(128) float g_hs1[N_NODES * HID];    // (x@W1)*dinv[row]
__device__ __align__(128) float g_z1[N_NODES * HID];     // conv1 result pre-bias
__device__ __align__(128) float g_hs2[N_NODES * HID];    // (z@W2)*dinv[row]
__device__ float g_sums[64];                             // [0:32) sum, [32:64) sumsq
__device__ float g_bn[64];                               // [0:32) scale, [32:64) shift

// ---------------------------------------------------------------
// 1) init
__global__ void k_init() {
    int i = blockIdx.x * blockDim.x + threadIdx.x;
    if (i < N_NODES) g_cnt[i] = 0;
    if (i < 64) g_sums[i] = 0.0f;
}

// 2) fill: bucket src ids by dst (4 edges per thread, vector index loads)
__global__ void k_fill(const int* __restrict__ src, const int* __restrict__ dst) {
    int t = blockIdx.x * blockDim.x + threadIdx.x;
    int e0 = t * 4;
    if (e0 >= N_EDGES) return;
    int4 d4 = *(const int4*)&dst[e0];
    int4 s4 = *(const int4*)&src[e0];
    int pos;
    pos = atomicAdd(&g_cnt[d4.x], 1); if (pos < CAP) g_slots[d4.x * CAP + pos] = s4.x;
    pos = atomicAdd(&g_cnt[d4.y], 1); if (pos < CAP) g_slots[d4.y * CAP + pos] = s4.y;
    pos = atomicAdd(&g_cnt[d4.z], 1); if (pos < CAP) g_slots[d4.z * CAP + pos] = s4.z;
    pos = atomicAdd(&g_cnt[d4.w], 1); if (pos < CAP) g_slots[d4.w * CAP + pos] = s4.w;
}

// ---------------------------------------------------------------
// 3) GEMM1: hs1[r] = (x[r] @ W1) * dinv[r]
__global__ void k_gemm1(const float* __restrict__ x, const float* __restrict__ W1) {
    __shared__ float Ws[IN_DIM * HID];   // 16KB
    __shared__ float Xs[128 * 36];       // 18KB padded
    int tid = threadIdx.x;
    int rowbase = blockIdx.x * 128;

    for (int i = tid; i < IN_DIM * HID / 4; i += 256)
        ((float4*)Ws)[i] = ((const float4*)W1)[i];

    int cg = tid & 7;    // cols cg*4..cg*4+3
    int rg = tid >> 3;   // rows rg*4..rg*4+3
    float acc[4][4] = {};

    for (int kb = 0; kb < IN_DIM; kb += 32) {
        __syncthreads();
        #pragma unroll
        for (int j = 0; j < 4; j++) {
            int idx = tid + j * 256;
            int r = idx >> 3, q = idx & 7;
            int gr = rowbase + r;
            float4 v = make_float4(0.f, 0.f, 0.f, 0.f);
            if (gr < N_NODES) v = *(const float4*)&x[(size_t)gr * IN_DIM + kb + q * 4];
            *(float4*)&Xs[r * 36 + q * 4] = v;
        }
        __syncthreads();
        #pragma unroll
        for (int k = 0; k < 32; k++) {
            float4 b4 = *(const float4*)&Ws[(kb + k) * HID + cg * 4];
            #pragma unroll
            for (int ri = 0; ri < 4; ri++) {
                float a = Xs[(rg * 4 + ri) * 36 + k];
                acc[ri][0] += a * b4.x; acc[ri][1] += a * b4.y;
                acc[ri][2] += a * b4.z; acc[ri][3] += a * b4.w;
            }
        }
    }
    #pragma unroll
    for (int ri = 0; ri < 4; ri++) {
        int r = rowbase + rg * 4 + ri;
        if (r < N_NODES) {
            float dinv = rsqrtf(1.0f + (float)g_cnt[r]);
            float4 v = make_float4(acc[ri][0] * dinv, acc[ri][1] * dinv,
                                   acc[ri][2] * dinv, acc[ri][3] * dinv);
            *(float4*)&g_hs1[r * HID + cg * 4] = v;
        }
    }
}

// ---------------------------------------------------------------
// pull body: one warp per node, lane = channel.
// Slot indices read as uniform-address int4 (warp broadcast) -> 4 independent
// gathers in flight per iteration, no shuffles.
__device__ __forceinline__ float pull_node(const float* __restrict__ hs, int n, int lane) {
    int cnt = g_cnt[n];
    int rem = min(cnt, CAP);
    float acc = hs[(size_t)n * HID + lane];
    const int* base = &g_slots[(size_t)n * CAP];
    float a0 = 0.f, a1 = 0.f, a2 = 0.f, a3 = 0.f;
    int j = 0;
    for (; j + 4 <= rem; j += 4) {
        int4 s4 = *(const int4*)&base[j];   // uniform address: broadcast
        a0 += hs[(size_t)s4.x * HID + lane];
        a1 += hs[(size_t)s4.y * HID + lane];
        a2 += hs[(size_t)s4.z * HID + lane];
        a3 += hs[(size_t)s4.w * HID + lane];
    }
    for (; j < rem; j++)
        acc += hs[(size_t)base[j] * HID + lane];
    acc += (a0 + a1) + (a2 + a3);
    return acc * rsqrtf(1.0f + (float)cnt);
}

// 4) pull1: z1 = D^{-1/2}(A+I)D^{-1/2} (x W1)
__global__ void k_pull1() {
    int w = (blockIdx.x * blockDim.x + threadIdx.x) >> 5;
    int lane = threadIdx.x & 31;
    if (w >= N_NODES) return;
    g_z1[(size_t)w * HID + lane] = pull_node(g_hs1, w, lane);
}

// 8) pull2: out = D^{-1/2}(A+I)D^{-1/2} (z W2) + b2
__global__ void k_pull2(const float* __restrict__ b2, float* __restrict__ out) {
    int w = (blockIdx.x * blockDim.x + threadIdx.x) >> 5;
    int lane = threadIdx.x & 31;
    if (w >= N_NODES) return;
    out[(size_t)w * HID + lane] = pull_node(g_hs2, w, lane) + b2[lane];
}

// ---------------------------------------------------------------
// 5) BN stats over v = z1 + b1
__global__ void k_bnstats(const float* __restrict__ b1) {
    __shared__ float ss[256], sq[256];
    int tid = threadIdx.x;
    int c = tid & 31, rs = tid >> 5;
    int chunk = (N_NODES + gridDim.x - 1) / gridDim.x;
    int r0 = blockIdx.x * chunk;
    int r1 = min(r0 + chunk, N_NODES);
    float bc = b1[c];
    float s = 0.f, s2 = 0.f;
    for (int r = r0 + rs; r < r1; r += 8) {
        float v = g_z1[(size_t)r * HID + c] + bc;
        s += v; s2 += v * v;
    }
    ss[tid] = s; sq[tid] = s2;
    __syncthreads();
    if (tid < 128) { ss[tid] += ss[tid + 128]; sq[tid] += sq[tid + 128]; }
    __syncthreads();
    if (tid < 64) { ss[tid] += ss[tid + 64]; sq[tid] += sq[tid + 64]; }
    __syncthreads();
    if (tid < 32) {
        atomicAdd(&g_sums[c], ss[tid] + ss[tid + 32]);
        atomicAdd(&g_sums[32 + c], sq[tid] + sq[tid + 32]);
    }
}

// 6) BN finalize
__global__ void k_bnfin(const float* __restrict__ gamma, const float* __restrict__ beta) {
    int c = threadIdx.x;
    if (c < 32) {
        float mean = g_sums[c] * (1.0f / N_NODES);
        float var = g_sums[32 + c] * (1.0f / N_NODES) - mean * mean;
        var = fmaxf(var, 0.f);
        float sc = gamma[c] * rsqrtf(var + BN_EPS);
        g_bn[c] = sc;
        g_bn[32 + c] = beta[c] - mean * sc;
    }
}

// ---------------------------------------------------------------
// 7) GEMM2: z = relu(BN(z1 + b1)); hs2 = (z@W2)*dinv
__global__ void k_gemm2(const float* __restrict__ b1, const float* __restrict__ W2) {
    __shared__ float Ws[HID * HID];   // 4KB
    __shared__ float Zs[128 * 36];    // 18KB
    __shared__ float sc_s[32], sh_s[32], bb_s[32];
    int tid = threadIdx.x;
    int rowbase = blockIdx.x * 128;

    if (tid < 32) { sc_s[tid] = g_bn[tid]; sh_s[tid] = g_bn[32 + tid]; bb_s[tid] = b1[tid]; }
    for (int i = tid; i < HID * HID / 4; i += 256)
        ((float4*)Ws)[i] = ((const float4*)W2)[i];
    __syncthreads();

    #pragma unroll
    for (int j = 0; j < 4; j++) {
        int idx = tid + j * 256;
        int r = idx >> 3, q = idx & 7;
        int gr = rowbase + r;
        float4 v = make_float4(0.f, 0.f, 0.f, 0.f);
        if (gr < N_NODES) {
            float4 a = *(const float4*)&g_z1[(size_t)gr * HID + q * 4];
            int c = q * 4;
            v.x = fmaxf(fmaf(a.x + bb_s[c + 0], sc_s[c + 0], sh_s[c + 0]), 0.f);
            v.y = fmaxf(fmaf(a.y + bb_s[c + 1], sc_s[c + 1], sh_s[c + 1]), 0.f);
            v.z = fmaxf(fmaf(a.z + bb_s[c + 2], sc_s[c + 2], sh_s[c + 2]), 0.f);
            v.w = fmaxf(fmaf(a.w + bb_s[c + 3], sc_s[c + 3], sh_s[c + 3]), 0.f);
        }
        *(float4*)&Zs[r * 36 + q * 4] = v;
    }
    __syncthreads();

    int cg = tid & 7, rg = tid >> 3;
    float acc[4][4] = {};
    #pragma unroll
    for (int k = 0; k < 32; k++) {
        float4 b4 = *(const float4*)&Ws[k * HID + cg * 4];
        #pragma unroll
        for (int ri = 0; ri < 4; ri++) {
            float a = Zs[(rg * 4 + ri) * 36 + k];
            acc[ri][0] += a * b4.x; acc[ri][1] += a * b4.y;
            acc[ri][2] += a * b4.z; acc[ri][3] += a * b4.w;
        }
    }
    #pragma unroll
    for (int ri = 0; ri < 4; ri++) {
        int r = rowbase + rg * 4 + ri;
        if (r < N_NODES) {
            float dinv = rsqrtf(1.0f + (float)g_cnt[r]);
            float4 v = make_float4(acc[ri][0] * dinv, acc[ri][1] * dinv,
                                   acc[ri][2] * dinv, acc[ri][3] * dinv);
            *(float4*)&g_hs2[r * HID + cg * 4] = v;
        }
    }
}

// ---------------------------------------------------------------
extern "C" void kernel_launch(void* const* d_in, const int* in_sizes, int n_in,
                              void* d_out, int out_size) {
    const float* x     = (const float*)d_in[0];
    const int*   ei    = (const int*)d_in[1];   // int32
    const float* W1    = (const float*)d_in[2];
    const float* b1    = (const float*)d_in[3];
    const float* gamma = (const float*)d_in[4];
    const float* beta  = (const float*)d_in[5];
    const float* W2    = (const float*)d_in[6];
    const float* b2    = (const float*)d_in[7];
    float* out = (float*)d_out;

    const int* esrc = ei;
    const int* edst = ei + N_EDGES;

    k_init   <<<(N_NODES + 255) / 256, 256>>>();
    k_fill   <<<(N_EDGES / 4 + 255) / 256, 256>>>(esrc, edst);
    k_gemm1  <<<(N_NODES + 127) / 128, 256>>>(x, W1);
    k_pull1  <<<(N_NODES * 32) / 256, 256>>>();
    k_bnstats<<<592, 256>>>(b1);
    k_bnfin  <<<1, 32>>>(gamma, beta);
    k_gemm2  <<<(N_NODES + 127) / 128, 256>>>(b1, W2);
    k_pull2  <<<(N_NODES * 32) / 256, 256>>>(b2, out);
}

// round 5
// speedup vs baseline: 1.1390x; 1.1390x over previous
#include <cuda_runtime.h>

#define N_NODES 100000
#define N_EDGES 1600000
#define IN_DIM 128
#define HID 32
#define BN_EPS 1e-5f
#define CAP 96   // max in-degree capacity (Poisson(16); P(deg>=96) ~ 1e-46); 16B-aligned, %4==0

// ---- scratch (static device globals; no allocation allowed) ----
__device__ __align__(128) int   g_cnt[N_NODES];          // in-degree (excl. self loop)
__device__ __align__(128) int   g_slots[N_NODES * CAP];  // buckets: src ids per dst
__device__ __align__(128) float g_hs1[N_NODES * HID];    // (x@W1)*dinv[row]
__device__ __align__(128) float g_z1[N_NODES * HID];     // conv1 result pre-bias
__device__ __align__(128) float g_hs2[N_NODES * HID];    // (z@W2)*dinv[row]
__device__ float g_sums[64];                             // [0:32) sum, [32:64) sumsq
__device__ float g_bn[64];                               // [0:32) scale, [32:64) shift

// ---------------------------------------------------------------
// 1) init
__global__ void k_init() {
    int i = blockIdx.x * blockDim.x + threadIdx.x;
    if (i < N_NODES) g_cnt[i] = 0;
    if (i < 64) g_sums[i] = 0.0f;
}

// 2) fill: bucket src ids by dst (4 edges per thread, vector index loads)
__global__ void k_fill(const int* __restrict__ src, const int* __restrict__ dst) {
    int t = blockIdx.x * blockDim.x + threadIdx.x;
    int e0 = t * 4;
    if (e0 >= N_EDGES) return;
    int4 d4 = *(const int4*)&dst[e0];
    int4 s4 = *(const int4*)&src[e0];
    int pos;
    pos = atomicAdd(&g_cnt[d4.x], 1); if (pos < CAP) g_slots[d4.x * CAP + pos] = s4.x;
    pos = atomicAdd(&g_cnt[d4.y], 1); if (pos < CAP) g_slots[d4.y * CAP + pos] = s4.y;
    pos = atomicAdd(&g_cnt[d4.z], 1); if (pos < CAP) g_slots[d4.z * CAP + pos] = s4.z;
    pos = atomicAdd(&g_cnt[d4.w], 1); if (pos < CAP) g_slots[d4.w * CAP + pos] = s4.w;
}

// ---------------------------------------------------------------
// 3) GEMM1: hs1[r] = (x[r] @ W1) * dinv[r]
__global__ void k_gemm1(const float* __restrict__ x, const float* __restrict__ W1) {
    __shared__ float Ws[IN_DIM * HID];   // 16KB
    __shared__ float Xs[128 * 36];       // 18KB padded
    int tid = threadIdx.x;
    int rowbase = blockIdx.x * 128;

    for (int i = tid; i < IN_DIM * HID / 4; i += 256)
        ((float4*)Ws)[i] = ((const float4*)W1)[i];

    int cg = tid & 7;    // cols cg*4..cg*4+3
    int rg = tid >> 3;   // rows rg*4..rg*4+3
    float acc[4][4] = {};

    for (int kb = 0; kb < IN_DIM; kb += 32) {
        __syncthreads();
        #pragma unroll
        for (int j = 0; j < 4; j++) {
            int idx = tid + j * 256;
            int r = idx >> 3, q = idx & 7;
            int gr = rowbase + r;
            float4 v = make_float4(0.f, 0.f, 0.f, 0.f);
            if (gr < N_NODES) v = *(const float4*)&x[(size_t)gr * IN_DIM + kb + q * 4];
            *(float4*)&Xs[r * 36 + q * 4] = v;
        }
        __syncthreads();
        #pragma unroll
        for (int k = 0; k < 32; k++) {
            float4 b4 = *(const float4*)&Ws[(kb + k) * HID + cg * 4];
            #pragma unroll
            for (int ri = 0; ri < 4; ri++) {
                float a = Xs[(rg * 4 + ri) * 36 + k];
                acc[ri][0] += a * b4.x; acc[ri][1] += a * b4.y;
                acc[ri][2] += a * b4.z; acc[ri][3] += a * b4.w;
            }
        }
    }
    #pragma unroll
    for (int ri = 0; ri < 4; ri++) {
        int r = rowbase + rg * 4 + ri;
        if (r < N_NODES) {
            float dinv = rsqrtf(1.0f + (float)g_cnt[r]);
            float4 v = make_float4(acc[ri][0] * dinv, acc[ri][1] * dinv,
                                   acc[ri][2] * dinv, acc[ri][3] * dinv);
            *(float4*)&g_hs1[r * HID + cg * 4] = v;
        }
    }
}

// ---------------------------------------------------------------
// pull body: one warp per node, 4 subwarps x 8 lanes.
// Subwarp sw handles edge j0+sw; each lane loads a float4 (8 lanes = 128B row).
// One LDG.128 warp-instruction gathers 4 edges -> ~2.5 instrs/edge.
__device__ __forceinline__ float4 pull_node(const float* __restrict__ hs, int n, int lane) {
    int cnt = g_cnt[n];
    int rem = min(cnt, CAP);
    int sw = lane >> 3;          // subwarp 0..3 -> edge within group
    int q  = lane & 7;           // float4 slot within row
    const int* base = &g_slots[(size_t)n * CAP];

    float4 acc;
    if (sw == 0) {               // self loop handled by subwarp 0
        acc = *(const float4*)&hs[(size_t)n * HID + q * 4];
    } else {
        acc = make_float4(0.f, 0.f, 0.f, 0.f);
    }

    for (int j0 = 0; j0 < rem; j0 += 4) {
        int jj = j0 + sw;
        if (jj < rem) {
            int s = base[jj];    // 8-way broadcast per subwarp, 1 wavefront/warp
            float4 v = *(const float4*)&hs[(size_t)s * HID + q * 4];
            acc.x += v.x; acc.y += v.y; acc.z += v.z; acc.w += v.w;
        }
    }

    // fold 4 subwarp partials: xor by 8 then 16
    #pragma unroll
    for (int off = 8; off <= 16; off <<= 1) {
        acc.x += __shfl_xor_sync(0xffffffffu, acc.x, off);
        acc.y += __shfl_xor_sync(0xffffffffu, acc.y, off);
        acc.z += __shfl_xor_sync(0xffffffffu, acc.z, off);
        acc.w += __shfl_xor_sync(0xffffffffu, acc.w, off);
    }
    float dinv = rsqrtf(1.0f + (float)cnt);
    acc.x *= dinv; acc.y *= dinv; acc.z *= dinv; acc.w *= dinv;
    return acc;
}

// 4) pull1: z1 = D^{-1/2}(A+I)D^{-1/2} (x W1)
__global__ void k_pull1() {
    int w = (blockIdx.x * blockDim.x + threadIdx.x) >> 5;
    int lane = threadIdx.x & 31;
    if (w >= N_NODES) return;
    float4 r = pull_node(g_hs1, w, lane);
    if (lane < 8)
        *(float4*)&g_z1[(size_t)w * HID + lane * 4] = r;
}

// 8) pull2: out = D^{-1/2}(A+I)D^{-1/2} (z W2) + b2
__global__ void k_pull2(const float* __restrict__ b2, float* __restrict__ out) {
    int w = (blockIdx.x * blockDim.x + threadIdx.x) >> 5;
    int lane = threadIdx.x & 31;
    if (w >= N_NODES) return;
    float4 r = pull_node(g_hs2, w, lane);
    if (lane < 8) {
        float4 bb = *(const float4*)&b2[lane * 4];
        r.x += bb.x; r.y += bb.y; r.z += bb.z; r.w += bb.w;
        *(float4*)&out[(size_t)w * HID + lane * 4] = r;
    }
}

// ---------------------------------------------------------------
// 5) BN stats over v = z1 + b1
__global__ void k_bnstats(const float* __restrict__ b1) {
    __shared__ float ss[256], sq[256];
    int tid = threadIdx.x;
    int c = tid & 31, rs = tid >> 5;
    int chunk = (N_NODES + gridDim.x - 1) / gridDim.x;
    int r0 = blockIdx.x * chunk;
    int r1 = min(r0 + chunk, N_NODES);
    float bc = b1[c];
    float s = 0.f, s2 = 0.f;
    for (int r = r0 + rs; r < r1; r += 8) {
        float v = g_z1[(size_t)r * HID + c] + bc;
        s += v; s2 += v * v;
    }
    ss[tid] = s; sq[tid] = s2;
    __syncthreads();
    if (tid < 128) { ss[tid] += ss[tid + 128]; sq[tid] += sq[tid + 128]; }
    __syncthreads();
    if (tid < 64) { ss[tid] += ss[tid + 64]; sq[tid] += sq[tid + 64]; }
    __syncthreads();
    if (tid < 32) {
        atomicAdd(&g_sums[c], ss[tid] + ss[tid + 32]);
        atomicAdd(&g_sums[32 + c], sq[tid] + sq[tid + 32]);
    }
}

// 6) BN finalize
__global__ void k_bnfin(const float* __restrict__ gamma, const float* __restrict__ beta) {
    int c = threadIdx.x;
    if (c < 32) {
        float mean = g_sums[c] * (1.0f / N_NODES);
        float var = g_sums[32 + c] * (1.0f / N_NODES) - mean * mean;
        var = fmaxf(var, 0.f);
        float sc = gamma[c] * rsqrtf(var + BN_EPS);
        g_bn[c] = sc;
        g_bn[32 + c] = beta[c] - mean * sc;
    }
}

// ---------------------------------------------------------------
// 7) GEMM2: z = relu(BN(z1 + b1)); hs2 = (z@W2)*dinv
__global__ void k_gemm2(const float* __restrict__ b1, const float* __restrict__ W2) {
    __shared__ float Ws[HID * HID];   // 4KB
    __shared__ float Zs[128 * 36];    // 18KB
    __shared__ float sc_s[32], sh_s[32], bb_s[32];
    int tid = threadIdx.x;
    int rowbase = blockIdx.x * 128;

    if (tid < 32) { sc_s[tid] = g_bn[tid]; sh_s[tid] = g_bn[32 + tid]; bb_s[tid] = b1[tid]; }
    for (int i = tid; i < HID * HID / 4; i += 256)
        ((float4*)Ws)[i] = ((const float4*)W2)[i];
    __syncthreads();

    #pragma unroll
    for (int j = 0; j < 4; j++) {
        int idx = tid + j * 256;
        int r = idx >> 3, q = idx & 7;
        int gr = rowbase + r;
        float4 v = make_float4(0.f, 0.f, 0.f, 0.f);
        if (gr < N_NODES) {
            float4 a = *(const float4*)&g_z1[(size_t)gr * HID + q * 4];
            int c = q * 4;
            v.x = fmaxf(fmaf(a.x + bb_s[c + 0], sc_s[c + 0], sh_s[c + 0]), 0.f);
            v.y = fmaxf(fmaf(a.y + bb_s[c + 1], sc_s[c + 1], sh_s[c + 1]), 0.f);
            v.z = fmaxf(fmaf(a.z + bb_s[c + 2], sc_s[c + 2], sh_s[c + 2]), 0.f);
            v.w = fmaxf(fmaf(a.w + bb_s[c + 3], sc_s[c + 3], sh_s[c + 3]), 0.f);
        }
        *(float4*)&Zs[r * 36 + q * 4] = v;
    }
    __syncthreads();

    int cg = tid & 7, rg = tid >> 3;
    float acc[4][4] = {};
    #pragma unroll
    for (int k = 0; k < 32; k++) {
        float4 b4 = *(const float4*)&Ws[k * HID + cg * 4];
        #pragma unroll
        for (int ri = 0; ri < 4; ri++) {
            float a = Zs[(rg * 4 + ri) * 36 + k];
            acc[ri][0] += a * b4.x; acc[ri][1] += a * b4.y;
            acc[ri][2] += a * b4.z; acc[ri][3] += a * b4.w;
        }
    }
    #pragma unroll
    for (int ri = 0; ri < 4; ri++) {
        int r = rowbase + rg * 4 + ri;
        if (r < N_NODES) {
            float dinv = rsqrtf(1.0f + (float)g_cnt[r]);
            float4 v = make_float4(acc[ri][0] * dinv, acc[ri][1] * dinv,
                                   acc[ri][2] * dinv, acc[ri][3] * dinv);
            *(float4*)&g_hs2[r * HID + cg * 4] = v;
        }
    }
}

// ---------------------------------------------------------------
extern "C" void kernel_launch(void* const* d_in, const int* in_sizes, int n_in,
                              void* d_out, int out_size) {
    const float* x     = (const float*)d_in[0];
    const int*   ei    = (const int*)d_in[1];   // int32
    const float* W1    = (const float*)d_in[2];
    const float* b1    = (const float*)d_in[3];
    const float* gamma = (const float*)d_in[4];
    const float* beta  = (const float*)d_in[5];
    const float* W2    = (const float*)d_in[6];
    const float* b2    = (const float*)d_in[7];
    float* out = (float*)d_out;

    const int* esrc = ei;
    const int* edst = ei + N_EDGES;

    k_init   <<<(N_NODES + 255) / 256, 256>>>();
    k_fill   <<<(N_EDGES / 4 + 255) / 256, 256>>>(esrc, edst);
    k_gemm1  <<<(N_NODES + 127) / 128, 256>>>(x, W1);
    k_pull1  <<<(N_NODES * 32) / 256, 256>>>();
    k_bnstats<<<592, 256>>>(b1);
    k_bnfin  <<<1, 32>>>(gamma, beta);
    k_gemm2  <<<(N_NODES + 127) / 128, 256>>>(b1, W2);
    k_pull2  <<<(N_NODES * 32) / 256, 256>>>(b2, out);
}